// round 2
// baseline (speedup 1.0000x reference)
#include <cuda_runtime.h>
#include <math.h>

#define NQ   12
#define NL   6
#define NC   64
#define TPB  256
#define APT  16      // amplitudes per thread (4096 / 256)

// State layout: flat index i in [0,4096), wire w <-> bit (11-w) (wire 0 = MSB).
// i = (tid << 4) | k :
//   bits 0-3  (wires 11..8) -> per-thread local register index k
//   bits 4-8  (wires  7..3) -> lane id (shuffle exchanges)
//   bits 9-11 (wires  2..0) -> warp id (smem exchanges)

__global__ __launch_bounds__(TPB, 2)
void qnn_kernel(const float* __restrict__ x,
                const float* __restrict__ qw,
                const float* __restrict__ W,
                const float* __restrict__ bias,
                float* __restrict__ out)
{
    // padded state mirror: thread t's amp k at sm[t*17 + k] -> conflict-free 64-bit LDS/STS
    __shared__ float2 sm[TPB * 17];
    __shared__ float cx[NQ], sx[NQ];
    __shared__ float cq[NL * NQ], sq[NL * NQ];
    __shared__ float red[8][NQ];
    __shared__ float zf[NQ];

    const int tid  = threadIdx.x;
    const int bsmp = blockIdx.x;           // batch sample
    const int lane = tid & 31;
    const int warp = tid >> 5;

    // per-sample embedding angles + shared layer angles (half angles)
    if (tid < NQ) {
        float s, c;
        sincosf(0.5f * x[bsmp * NQ + tid], &s, &c);
        cx[tid] = c; sx[tid] = s;
    }
    if (tid >= 32 && tid < 32 + NL * NQ) {
        int idx = tid - 32;
        float s, c;
        sincosf(0.5f * qw[idx], &s, &c);
        cq[idx] = c; sq[idx] = s;
    }
    __syncthreads();

    // ---- init: fused AngleEmbedding product state + CNOT-ring permutation sources ----
    float2 a[APT];
    int    src[APT];
    const int base = tid << 4;

#pragma unroll
    for (int k = 0; k < APT; ++k) {
        const int i = base | k;
        float mag = 1.0f;
#pragma unroll
        for (int w = 0; w < NQ; ++w) {
            const int bit = (i >> (11 - w)) & 1;
            mag *= bit ? sx[w] : cx[w];
        }
        const int pc = __popc(i) & 3;       // amp = mag * (-i)^popcount
        float re = 0.f, im = 0.f;
        if      (pc == 0) re =  mag;
        else if (pc == 1) im = -mag;
        else if (pc == 2) re = -mag;
        else              im =  mag;
        a[k] = make_float2(re, im);

        // src(i): inverse of the layer's CNOT ring (CNOT(w, (w+1)%12), w = 0..11 in order)
        int j = i;
#pragma unroll
        for (int w = NQ - 1; w >= 0; --w) {
            const int t  = (w + 1) % NQ;
            const int bc = (j >> (11 - w)) & 1;
            j ^= bc << (11 - t);
        }
        src[k] = j;
    }

    // ---- 6 entangler layers ----
#pragma unroll 1
    for (int l = 0; l < NL; ++l) {
        const float* cl = &cq[l * NQ];
        const float* sl = &sq[l * NQ];

        // RX on wires 8..11 : local register pairs (bit 3..0 of k)
#pragma unroll
        for (int w = 8; w < 12; ++w) {
            const int   m = 1 << (11 - w);
            const float c = cl[w], s = sl[w];
#pragma unroll
            for (int k0 = 0; k0 < APT; ++k0) {
                if (k0 & m) continue;
                const int k1 = k0 | m;
                const float2 t0 = a[k0], t1 = a[k1];
                a[k0] = make_float2(fmaf(c, t0.x,  s * t1.y), fmaf(c, t0.y, -s * t1.x));
                a[k1] = make_float2(fmaf(c, t1.x,  s * t0.y), fmaf(c, t1.y, -s * t0.x));
            }
        }

        // RX on wires 3..7 : lane-bit butterflies via shuffle
#pragma unroll
        for (int w = 3; w < 8; ++w) {
            const int   m = 1 << (7 - w);
            const float c = cl[w], s = sl[w];
#pragma unroll
            for (int k = 0; k < APT; ++k) {
                const float pr = __shfl_xor_sync(0xffffffffu, a[k].x, m);
                const float pi = __shfl_xor_sync(0xffffffffu, a[k].y, m);
                a[k] = make_float2(fmaf(c, a[k].x,  s * pi), fmaf(c, a[k].y, -s * pr));
            }
        }

        // RX on wires 0..2 : warp-bit exchange via padded smem
#pragma unroll
        for (int w = 0; w < 3; ++w) {
            const int   pt = tid ^ (1 << (7 - w));
            const float c  = cl[w], s = sl[w];
            __syncthreads();
#pragma unroll
            for (int k = 0; k < APT; ++k) sm[tid * 17 + k] = a[k];
            __syncthreads();
#pragma unroll
            for (int k = 0; k < APT; ++k) {
                const float2 p = sm[pt * 17 + k];
                a[k] = make_float2(fmaf(c, a[k].x,  s * p.y), fmaf(c, a[k].y, -s * p.x));
            }
        }

        // 12 ring CNOTs fused into one permutation gather
        __syncthreads();
#pragma unroll
        for (int k = 0; k < APT; ++k) sm[tid * 17 + k] = a[k];
        __syncthreads();
#pragma unroll
        for (int k = 0; k < APT; ++k) {
            const int j = src[k];
            a[k] = sm[(j >> 4) * 17 + (j & 15)];
        }
    }

    // ---- <Z_w> readout ----
    float ptot = 0.f;
    float zl[4] = {0.f, 0.f, 0.f, 0.f};     // wires 8..11 (sign varies with k)
#pragma unroll
    for (int k = 0; k < APT; ++k) {
        const float p = a[k].x * a[k].x + a[k].y * a[k].y;
        ptot += p;
#pragma unroll
        for (int w = 8; w < 12; ++w)
            zl[w - 8] += ((k >> (11 - w)) & 1) ? -p : p;
    }

    float z12[NQ];
#pragma unroll
    for (int w = 0; w < 8; ++w)            // wires 0..7: sign fixed per thread
        z12[w] = ((tid >> (7 - w)) & 1) ? -ptot : ptot;
#pragma unroll
    for (int w = 8; w < 12; ++w) z12[w] = zl[w - 8];

    // warp tree-reduce all 12 values
#pragma unroll
    for (int w = 0; w < NQ; ++w) {
#pragma unroll
        for (int o = 16; o > 0; o >>= 1)
            z12[w] += __shfl_xor_sync(0xffffffffu, z12[w], o);
    }
    if (lane == 0) {
#pragma unroll
        for (int w = 0; w < NQ; ++w) red[warp][w] = z12[w];
    }
    __syncthreads();
    if (tid < NQ) {
        float acc = 0.f;
#pragma unroll
        for (int ww = 0; ww < 8; ++ww) acc += red[ww][tid];
        zf[tid] = acc;
    }
    __syncthreads();

    // ---- classifier head: out[b, c] = b[c] + sum_w z[w] * W[c, w] ----
    if (tid < NC) {
        float acc = bias[tid];
#pragma unroll
        for (int w = 0; w < NQ; ++w)
            acc = fmaf(zf[w], W[tid * NQ + w], acc);
        out[bsmp * NC + tid] = acc;
    }
}

extern "C" void kernel_launch(void* const* d_in, const int* in_sizes, int n_in,
                              void* d_out, int out_size)
{
    const float* x  = (const float*)d_in[0];   // (512, 12)
    const float* qw = (const float*)d_in[1];   // (6, 12)
    const float* W  = (const float*)d_in[2];   // (64, 12)
    const float* bs = (const float*)d_in[3];   // (64,)
    float* out = (float*)d_out;                // (512, 64)
    qnn_kernel<<<512, TPB>>>(x, qw, W, bs, out);
}

// round 4
// speedup vs baseline: 1.6473x; 1.6473x over previous
#include <cuda_runtime.h>
#include <stdint.h>
#include <math.h>

#define NQ   12
#define NL   6
#define NC   64
#define TPB  256
#define APT  16        // amplitudes per thread (4096 / 256)
#define PAD  17        // padded row stride (float2) -> conflict-free half-warp phases
#define BUFSZ (TPB * PAD)   // 4352 float2 per buffer

// Amp index i (12 bits): wire w <-> bit (11-w) (wire 0 = MSB).
// Bit groups: A = bits 3..0 (wires 8-11), B = bits 7..4 (wires 4-7), C = bits 11..8 (wires 0-3).
// Layouts (thread T, local k):
//   M0: k = A, T = (C<<4)|B      (canonical; init / after each layer)
//   M1: k = B, T = (C<<4)|A
//   M2: k = C, T = (A<<4)|B

extern __shared__ float2 dynsm[];   // [2][BUFSZ] double-buffered state mirror

__device__ __forceinline__ void rx4(float2* a, const float* cl, const float* sl,
                                    int w0, int sh)
{
    // RX on 4 register-local wires: wire = w0 + n, local-bit mask = 1 << (sh - n)
#pragma unroll
    for (int n = 0; n < 4; ++n) {
        const int   m = 1 << (sh - n);
        const float c = cl[w0 + n], s = sl[w0 + n];
#pragma unroll
        for (int k0 = 0; k0 < APT; ++k0) {
            if (k0 & m) continue;
            const int k1 = k0 | m;
            const float2 t0 = a[k0], t1 = a[k1];
            a[k0] = make_float2(fmaf(c, t0.x,  s * t1.y), fmaf(c, t0.y, -s * t1.x));
            a[k1] = make_float2(fmaf(c, t1.x,  s * t0.y), fmaf(c, t1.y, -s * t0.x));
        }
    }
}

__global__ __launch_bounds__(TPB, 2)
void qnn_kernel(const float* __restrict__ x,
                const float* __restrict__ qw,
                const float* __restrict__ W,
                const float* __restrict__ bias,
                float* __restrict__ out)
{
    __shared__ float cx[NQ], sx[NQ];
    __shared__ float cq[NL * NQ], sq[NL * NQ];
    __shared__ float red[8][NQ];
    __shared__ float zf[NQ];

    float2* const buf0 = dynsm;
    float2* const buf1 = dynsm + BUFSZ;

    const int tid  = threadIdx.x;
    const int bsmp = blockIdx.x;
    const int lane = tid & 31;
    const int warp = tid >> 5;

    if (tid < NQ) {
        float s, c;
        sincosf(0.5f * x[bsmp * NQ + tid], &s, &c);
        cx[tid] = c; sx[tid] = s;
    }
    if (tid >= 32 && tid < 32 + NL * NQ) {
        const int idx = tid - 32;
        float s, c;
        sincosf(0.5f * qw[idx], &s, &c);
        cq[idx] = c; sq[idx] = s;
    }
    __syncthreads();

    // ---- init (layout M0): fused AngleEmbedding product state ----
    float2 a[APT];
    uint32_t off3p[APT / 2];      // packed Q3 gather offsets (two uint16 per reg)
    const int base = tid << 4;

#pragma unroll
    for (int k = 0; k < APT; ++k) {
        const int i = base | k;
        float mag = 1.0f;
#pragma unroll
        for (int w = 0; w < NQ; ++w)
            mag *= ((i >> (11 - w)) & 1) ? sx[w] : cx[w];
        const int pc = __popc(i) & 3;          // amp = mag * (-i)^popcount
        float re = 0.f, im = 0.f;
        if      (pc == 0) re =  mag;
        else if (pc == 1) im = -mag;
        else if (pc == 2) re = -mag;
        else              im =  mag;
        a[k] = make_float2(re, im);

        // sigma(i): gather index for the CNOT ring (CNOT(w,(w+1)%12), w ascending)
        int j = i;
#pragma unroll
        for (int w = NQ - 1; w >= 0; --w) {
            const int t  = (w + 1) % NQ;
            const int bc = (j >> (11 - w)) & 1;
            j ^= bc << (11 - t);
        }
        // amp j in layout M2: T'' = ((j&15)<<4)|((j>>4)&15), k'' = j>>8
        const uint32_t off = (uint32_t)((((j & 15) << 4) | ((j >> 4) & 15)) * PAD + (j >> 8));
        if (k & 1) off3p[k >> 1] |= off << 16;
        else       off3p[k >> 1]  = off;
    }

    const int wbase = tid * PAD;                                   // STS base (all rounds)
    const int q1b   = (tid & 0xF0) * PAD + (tid & 15);             // Q1 LDS base
    const int q2b   = (tid >> 4)   * PAD + (tid & 15);             // Q2 LDS base

    // ---- 6 entangler layers ----
#pragma unroll 1
    for (int l = 0; l < NL; ++l) {
        const float* cl = &cq[l * NQ];
        const float* sl = &sq[l * NQ];
        float2* const bA = (l & 1) ? buf1 : buf0;   // rounds Q1, Q3
        float2* const bB = (l & 1) ? buf0 : buf1;   // round  Q2

        // RX wires 8..11 (M0 local: wire w <-> bit 11-w)
        rx4(a, cl, sl, 8, 3);

        // Q1: M0 -> M1 (local bits become B = wires 4..7)
#pragma unroll
        for (int k = 0; k < APT; ++k) bA[wbase + k] = a[k];
        __syncthreads();
#pragma unroll
        for (int k = 0; k < APT; ++k) a[k] = bA[q1b + k * PAD];

        // RX wires 4..7 (M1 local: wire w <-> bit 7-w)
        rx4(a, cl, sl, 4, 3);

        // Q2: M1 -> M2 (local bits become C = wires 0..3)
#pragma unroll
        for (int k = 0; k < APT; ++k) bB[wbase + k] = a[k];
        __syncthreads();
#pragma unroll
        for (int k = 0; k < APT; ++k) a[k] = bB[q2b + k * (16 * PAD)];

        // RX wires 0..3 (M2 local: wire w <-> bit 3-w)
        rx4(a, cl, sl, 0, 3);

        // Q3: fused CNOT-ring permutation, M2 -> M0
#pragma unroll
        for (int k = 0; k < APT; ++k) bA[wbase + k] = a[k];
        __syncthreads();
#pragma unroll
        for (int k = 0; k < APT; ++k) {
            const uint32_t off = (k & 1) ? (off3p[k >> 1] >> 16)
                                         : (off3p[k >> 1] & 0xFFFFu);
            a[k] = bA[off];
        }
    }

    // ---- <Z_w> readout (layout M0) ----
    float ptot = 0.f;
    float zl[4] = {0.f, 0.f, 0.f, 0.f};
#pragma unroll
    for (int k = 0; k < APT; ++k) {
        const float p = a[k].x * a[k].x + a[k].y * a[k].y;
        ptot += p;
#pragma unroll
        for (int w = 8; w < 12; ++w)
            zl[w - 8] += ((k >> (11 - w)) & 1) ? -p : p;
    }

    float z12[NQ];
#pragma unroll
    for (int w = 0; w < 8; ++w)
        z12[w] = ((tid >> (7 - w)) & 1) ? -ptot : ptot;
#pragma unroll
    for (int w = 8; w < 12; ++w) z12[w] = zl[w - 8];

#pragma unroll
    for (int w = 0; w < NQ; ++w) {
#pragma unroll
        for (int o = 16; o > 0; o >>= 1)
            z12[w] += __shfl_xor_sync(0xffffffffu, z12[w], o);
    }
    if (lane == 0) {
#pragma unroll
        for (int w = 0; w < NQ; ++w) red[warp][w] = z12[w];
    }
    __syncthreads();
    if (tid < NQ) {
        float acc = 0.f;
#pragma unroll
        for (int ww = 0; ww < 8; ++ww) acc += red[ww][tid];
        zf[tid] = acc;
    }
    __syncthreads();

    // ---- classifier head ----
    if (tid < NC) {
        float acc = bias[tid];
#pragma unroll
        for (int w = 0; w < NQ; ++w)
            acc = fmaf(zf[w], W[tid * NQ + w], acc);
        out[bsmp * NC + tid] = acc;
    }
}

extern "C" void kernel_launch(void* const* d_in, const int* in_sizes, int n_in,
                              void* d_out, int out_size)
{
    const float* x  = (const float*)d_in[0];   // (512, 12)
    const float* qw = (const float*)d_in[1];   // (6, 12)
    const float* W  = (const float*)d_in[2];   // (64, 12)
    const float* bs = (const float*)d_in[3];   // (64,)
    float* out = (float*)d_out;                // (512, 64)

    const int smem = 2 * BUFSZ * (int)sizeof(float2);   // 69632 B
    cudaFuncSetAttribute(qnn_kernel, cudaFuncAttributeMaxDynamicSharedMemorySize, smem);
    qnn_kernel<<<512, TPB, smem>>>(x, qw, W, bs, out);
}